// round 13
// baseline (speedup 1.0000x reference)
#include <cuda_runtime.h>
#include <cuda_fp16.h>

// Problem constants (from reference setup_inputs)
#define Bn 8
#define Hn 768
#define Wn 768
#define NPIX (Bn * Hn * Wn)          // 4,718,592
#define HWn (Hn * Wn)
#define PROP_TIME 24
#define GROUP 4                       // per-group working set ~51MB, L2-resident

// 8 fp16 weights per pixel, one 16B vector load
struct __align__(16) W8 { __half2 h[4]; };

// Scratch: __device__ globals (allocation-free per harness rules).
__device__ W8     g_wh[NPIX];         // ~75.5 MB total, 37.7 MB per group
__device__ __half g_baseh[NPIX];      // ~9.4 MB (fp16 base)
__device__ __half g_bufA[NPIX];       // ~9.4 MB (fp16 state ping)
__device__ __half g_bufB[NPIX];       // ~9.4 MB (fp16 state pong)

// 8-neighbor offsets (dy, dx), reference order
__constant__ int c_dy[8] = {-5, -1, 0, 0, 5, 1,  0,  0};
__constant__ int c_dx[8] = { 0,  0, 5, 1, 0, 0, -5, -1};

// ---------------------------------------------------------------------------
// Fused precompute + first propagation step (per group).
// Computes fp16-rounded weights and fp16 base (from the ROUNDED weights),
// stores them for iterations 2..24, and directly emits
//   r1 = base + sum_c w_c * blur[neighbor_c]      (r0 == blur)
// r1 stored as fp16. mask px: w=0, base=raw -> r1 = raw (pinned).
// ---------------------------------------------------------------------------
__global__ void __launch_bounds__(512) fused_pre_prop1_kernel(
    const float* __restrict__ guid,
    const float* __restrict__ blur,
    const float* __restrict__ sparse,
    __half* __restrict__ rout,
    int b0)
{
    int x = blockIdx.x * 32 + threadIdx.x;
    int y = blockIdx.y * 16 + threadIdx.y;
    int b = b0 + blockIdx.z;

    size_t boff = (size_t)b * HWn;
    size_t i = boff + (size_t)y * Wn + x;
    const float* gb = guid + (size_t)b * 8 * HWn;
    const float* bb = blur + boff;

    float w[8];
    float s = 0.0f;
#pragma unroll
    for (int c = 0; c < 8; ++c) {
        int yy = y + c_dy[c];
        int xx = x + c_dx[c];
        float v = 0.0f;
        if ((unsigned)yy < (unsigned)Hn && (unsigned)xx < (unsigned)Wn)
            v = __ldcs(&gb[(size_t)c * HWn + yy * Wn + xx]);
        w[c] = v;
        s += fabsf(v);
    }
    float inv = 1.0f / fmaxf(s, 1e-6f);
#pragma unroll
    for (int c = 0; c < 8; ++c) w[c] *= inv;

    float raw  = __ldcs(&blur[i]);
    bool  mask = __ldcs(&sparse[i]) > 0.0f;   // sign() of a non-negative field

    if (mask) {
#pragma unroll
        for (int c = 0; c < 8; ++c) w[c] = 0.0f;
    }

    // round weights to fp16; gate_sum from the ROUNDED weights
    W8 pack;
    float wr[8];
    float gs = 0.0f;
#pragma unroll
    for (int c = 0; c < 4; ++c) {
        __half2 h = __floats2half2_rn(w[2 * c], w[2 * c + 1]);
        pack.h[c] = h;
        float2 back = __half22float2(h);
        wr[2 * c]     = back.x;
        wr[2 * c + 1] = back.y;
        gs += back.x + back.y;
    }

    // base rounded to fp16; use the ROUNDED value everywhere for consistency
    float basef_full = mask ? raw : (1.0f - gs) * raw;
    __half bh = __float2half_rn(basef_full);
    float basef = __half2float(bh);

    g_wh[i]     = pack;
    g_baseh[i]  = bh;

    // r1 = base + sum_c w_c * blur_tap_c   (zero padding outside image)
    int yw = y * Wn;
    float up5 = (y >= 5)      ? __ldcs(&bb[yw - 5 * Wn + x]) : 0.0f;
    float up1 = (y >= 1)      ? __ldcs(&bb[yw - Wn + x])     : 0.0f;
    float rt5 = (x + 5 < Wn)  ? __ldcs(&bb[yw + x + 5])      : 0.0f;
    float rt1 = (x + 1 < Wn)  ? __ldcs(&bb[yw + x + 1])      : 0.0f;
    float dn5 = (y + 5 < Hn)  ? __ldcs(&bb[yw + 5 * Wn + x]) : 0.0f;
    float dn1 = (y + 1 < Hn)  ? __ldcs(&bb[yw + Wn + x])     : 0.0f;
    float lf5 = (x >= 5)      ? __ldcs(&bb[yw + x - 5])      : 0.0f;
    float lf1 = (x >= 1)      ? __ldcs(&bb[yw + x - 1])      : 0.0f;

    float acc = basef;
    acc = fmaf(wr[0], up5, acc);
    acc = fmaf(wr[1], up1, acc);
    acc = fmaf(wr[2], rt5, acc);
    acc = fmaf(wr[3], rt1, acc);
    acc = fmaf(wr[4], dn5, acc);
    acc = fmaf(wr[5], dn1, acc);
    acc = fmaf(wr[6], lf5, acc);
    acc = fmaf(wr[7], lf1, acc);

    __stcg(&rout[i], __float2half_rn(acc));
}

// ---------------------------------------------------------------------------
// Shared body of one propagation step (fp16 state in, fp32 accumulate).
// ---------------------------------------------------------------------------
__device__ __forceinline__ float prop_body(const __half* __restrict__ rb,
                                           int x, int y, size_t i)
{
    int yw = y * Wn;

    float up5 = (y >= 5)      ? __half2float(__ldcs(&rb[yw - 5 * Wn + x])) : 0.0f;
    float up1 = (y >= 1)      ? __half2float(__ldcs(&rb[yw - Wn + x]))     : 0.0f;
    float rt5 = (x + 5 < Wn)  ? __half2float(__ldcs(&rb[yw + x + 5]))      : 0.0f;
    float rt1 = (x + 1 < Wn)  ? __half2float(__ldcs(&rb[yw + x + 1]))      : 0.0f;
    float dn5 = (y + 5 < Hn)  ? __half2float(__ldcs(&rb[yw + 5 * Wn + x])) : 0.0f;
    float dn1 = (y + 1 < Hn)  ? __half2float(__ldcs(&rb[yw + Wn + x]))     : 0.0f;
    float lf5 = (x >= 5)      ? __half2float(__ldcs(&rb[yw + x - 5]))      : 0.0f;
    float lf1 = (x >= 1)      ? __half2float(__ldcs(&rb[yw + x - 1]))      : 0.0f;

    uint4 u = __ldcg(reinterpret_cast<const uint4*>(&g_wh[i]));
    float2 w01 = __half22float2(*reinterpret_cast<__half2*>(&u.x));
    float2 w23 = __half22float2(*reinterpret_cast<__half2*>(&u.y));
    float2 w45 = __half22float2(*reinterpret_cast<__half2*>(&u.z));
    float2 w67 = __half22float2(*reinterpret_cast<__half2*>(&u.w));

    float acc = __half2float(__ldcg(&g_baseh[i]));
    acc = fmaf(w01.x, up5, acc);
    acc = fmaf(w01.y, up1, acc);
    acc = fmaf(w23.x, rt5, acc);
    acc = fmaf(w23.y, rt1, acc);
    acc = fmaf(w45.x, dn5, acc);
    acc = fmaf(w45.y, dn1, acc);
    acc = fmaf(w67.x, lf5, acc);
    acc = fmaf(w67.y, lf1, acc);
    return acc;
}

// Middle iterations: fp16 -> fp16
__global__ void __launch_bounds__(512) prop_kernel_h(const __half* __restrict__ rin,
                                                     __half* __restrict__ rout,
                                                     int b0)
{
    int x = blockIdx.x * 32 + threadIdx.x;
    int y = blockIdx.y * 16 + threadIdx.y;
    int b = b0 + blockIdx.z;
    size_t i = (size_t)b * HWn + (size_t)y * Wn + x;

    float acc = prop_body(rin + (size_t)b * HWn, x, y, i);
    __stcg(&rout[i], __float2half_rn(acc));
}

// Final iteration: fp16 -> fp32 (d_out)
__global__ void __launch_bounds__(512) prop_kernel_f(const __half* __restrict__ rin,
                                                     float* __restrict__ rout,
                                                     int b0)
{
    int x = blockIdx.x * 32 + threadIdx.x;
    int y = blockIdx.y * 16 + threadIdx.y;
    int b = b0 + blockIdx.z;
    size_t i = (size_t)b * HWn + (size_t)y * Wn + x;

    float acc = prop_body(rin + (size_t)b * HWn, x, y, i);
    __stcg(&rout[i], acc);
}

// ---------------------------------------------------------------------------
// Launch: per 4-batch group: fused precompute+iter1, then 22 fp16 prop steps,
// then a final fp16->fp32 step into d_out. Group weights/base/state ~51MB,
// comfortably L2-resident.
// ---------------------------------------------------------------------------
extern "C" void kernel_launch(void* const* d_in, const int* in_sizes, int n_in,
                              void* d_out, int out_size)
{
    const float* guid   = (const float*)d_in[0];   // (B,8,H,W)
    const float* blur   = (const float*)d_in[1];   // (B,1,H,W)
    const float* sparse = (const float*)d_in[2];   // (B,1,H,W)
    float* out = (float*)d_out;                    // (B,1,H,W)

    __half *bufA, *bufB;
    cudaGetSymbolAddress((void**)&bufA, g_bufA);
    cudaGetSymbolAddress((void**)&bufB, g_bufB);

    dim3 blk(32, 16);
    dim3 grd(Wn / 32, Hn / 16, GROUP);

    for (int g = 0; g < Bn / GROUP; ++g) {
        int b0 = g * GROUP;

        // iteration 1 fused with weight/base precompute (writes fp16 r1)
        fused_pre_prop1_kernel<<<grd, blk>>>(guid, blur, sparse, bufA, b0);
        const __half* cur = bufA;

        // iterations 2..23 (fp16 -> fp16)
        for (int it = 1; it < PROP_TIME - 1; ++it) {
            __half* dst = (it & 1) ? bufB : bufA;
            prop_kernel_h<<<grd, blk>>>(cur, dst, b0);
            cur = dst;
        }

        // iteration 24 (fp16 -> fp32 d_out)
        prop_kernel_f<<<grd, blk>>>(cur, out, b0);
    }
}

// round 15
// speedup vs baseline: 1.6612x; 1.6612x over previous
#include <cuda_runtime.h>
#include <cuda_fp16.h>

// Problem constants (from reference setup_inputs)
#define Bn 8
#define Hn 768
#define Wn 768
#define NPIX (Bn * Hn * Wn)          // 4,718,592
#define HWn (Hn * Wn)
#define PROP_TIME 24
#define GROUP 4                       // per-group working set ~47MB, L2-resident

// 8 fp16 weights per pixel, one 16B vector load
struct __align__(16) W8 { __half2 h[4]; };

// Scratch: __device__ globals (allocation-free per harness rules).
__device__ W8     g_wh[NPIX];         // ~75.5 MB total, 37.7 MB per group
__device__ __half g_baseh[NPIX];      // ~9.4 MB (fp16 base)
__device__ __half g_bufA[NPIX];       // ~9.4 MB (fp16 state ping)
__device__ __half g_bufB[NPIX];       // ~9.4 MB (fp16 state pong)

// 8-neighbor offsets (dy, dx), reference order
__constant__ int c_dy[8] = {-5, -1, 0, 0, 5, 1,  0,  0};
__constant__ int c_dx[8] = { 0,  0, 5, 1, 0, 0, -5, -1};

// ---------------------------------------------------------------------------
// Fused precompute + first propagation step (per group), 1 px/thread.
// fp16-rounded weights, fp16 base from ROUNDED weights, emits fp16 r1.
// ---------------------------------------------------------------------------
__global__ void __launch_bounds__(512) fused_pre_prop1_kernel(
    const float* __restrict__ guid,
    const float* __restrict__ blur,
    const float* __restrict__ sparse,
    __half* __restrict__ rout,
    int b0)
{
    int x = blockIdx.x * 32 + threadIdx.x;
    int y = blockIdx.y * 16 + threadIdx.y;
    int b = b0 + blockIdx.z;

    size_t boff = (size_t)b * HWn;
    size_t i = boff + (size_t)y * Wn + x;
    const float* gb = guid + (size_t)b * 8 * HWn;
    const float* bb = blur + boff;

    float w[8];
    float s = 0.0f;
#pragma unroll
    for (int c = 0; c < 8; ++c) {
        int yy = y + c_dy[c];
        int xx = x + c_dx[c];
        float v = 0.0f;
        if ((unsigned)yy < (unsigned)Hn && (unsigned)xx < (unsigned)Wn)
            v = __ldcs(&gb[(size_t)c * HWn + yy * Wn + xx]);
        w[c] = v;
        s += fabsf(v);
    }
    float inv = 1.0f / fmaxf(s, 1e-6f);
#pragma unroll
    for (int c = 0; c < 8; ++c) w[c] *= inv;

    float raw  = __ldcs(&blur[i]);
    bool  mask = __ldcs(&sparse[i]) > 0.0f;   // sign() of a non-negative field

    if (mask) {
#pragma unroll
        for (int c = 0; c < 8; ++c) w[c] = 0.0f;
    }

    // round weights to fp16; gate_sum from the ROUNDED weights
    W8 pack;
    float wr[8];
    float gs = 0.0f;
#pragma unroll
    for (int c = 0; c < 4; ++c) {
        __half2 h = __floats2half2_rn(w[2 * c], w[2 * c + 1]);
        pack.h[c] = h;
        float2 back = __half22float2(h);
        wr[2 * c]     = back.x;
        wr[2 * c + 1] = back.y;
        gs += back.x + back.y;
    }

    float basef_full = mask ? raw : (1.0f - gs) * raw;
    __half bh = __float2half_rn(basef_full);
    float basef = __half2float(bh);

    g_wh[i]    = pack;
    g_baseh[i] = bh;

    // r1 = base + sum_c w_c * blur_tap_c   (zero padding outside image)
    int yw = y * Wn;
    float up5 = (y >= 5)      ? __ldcs(&bb[yw - 5 * Wn + x]) : 0.0f;
    float up1 = (y >= 1)      ? __ldcs(&bb[yw - Wn + x])     : 0.0f;
    float rt5 = (x + 5 < Wn)  ? __ldcs(&bb[yw + x + 5])      : 0.0f;
    float rt1 = (x + 1 < Wn)  ? __ldcs(&bb[yw + x + 1])      : 0.0f;
    float dn5 = (y + 5 < Hn)  ? __ldcs(&bb[yw + 5 * Wn + x]) : 0.0f;
    float dn1 = (y + 1 < Hn)  ? __ldcs(&bb[yw + Wn + x])     : 0.0f;
    float lf5 = (x >= 5)      ? __ldcs(&bb[yw + x - 5])      : 0.0f;
    float lf1 = (x >= 1)      ? __ldcs(&bb[yw + x - 1])      : 0.0f;

    float acc = basef;
    acc = fmaf(wr[0], up5, acc);
    acc = fmaf(wr[1], up1, acc);
    acc = fmaf(wr[2], rt5, acc);
    acc = fmaf(wr[3], rt1, acc);
    acc = fmaf(wr[4], dn5, acc);
    acc = fmaf(wr[5], dn1, acc);
    acc = fmaf(wr[6], lf5, acc);
    acc = fmaf(wr[7], lf1, acc);

    rout[i] = __float2half_rn(acc);
}

// aligned __half2 load (evict-first) -> float2; zero if invalid
__device__ __forceinline__ float2 h2ld(const __half* p, bool ok)
{
    if (!ok) return make_float2(0.f, 0.f);
    unsigned u = __ldcs(reinterpret_cast<const unsigned*>(p));
    return __half22float2(*reinterpret_cast<__half2*>(&u));
}

// ---------------------------------------------------------------------------
// One propagation step, 2 x-adjacent px/thread, ALL accesses 32-bit+.
// Taps from aligned __half2 loads; weights 2x LDG.128; base __half2 (4B).
// ---------------------------------------------------------------------------
__device__ __forceinline__ float2 prop_body2(const __half* __restrict__ rb,
                                             int x0, int y, size_t i)
{
    const __half* row = rb + (size_t)y * Wn;

    // vertical taps (pairs, aligned since x0 even)
    float2 up5 = h2ld(row - 5 * Wn + x0, y >= 5);
    float2 up1 = h2ld(row - Wn + x0,     y >= 1);
    float2 dn5 = h2ld(row + 5 * Wn + x0, y + 5 < Hn);
    float2 dn1 = h2ld(row + Wn + x0,     y + 1 < Hn);

    // horizontal pairs: offsets x0-6 .. x0+6 step 2
    float2 pa = h2ld(row + x0 - 6, x0 >= 6);        // (x0-6, x0-5)
    float2 pb = h2ld(row + x0 - 4, x0 >= 4);        // (x0-4, x0-3)
    float2 pc = h2ld(row + x0 - 2, x0 >= 2);        // (x0-2, x0-1)
    float2 pd = h2ld(row + x0,     true);           // (x0,   x0+1)
    float2 pe = h2ld(row + x0 + 2, x0 + 2 < Wn);    // (x0+2, x0+3)
    float2 pf = h2ld(row + x0 + 4, x0 + 4 < Wn);    // (x0+4, x0+5)
    float2 pg = h2ld(row + x0 + 6, x0 + 6 < Wn);    // (x0+6, x0+7)

    // weights + base (L2-resident streams)
    uint4 u0 = __ldcg(reinterpret_cast<const uint4*>(&g_wh[i]));
    uint4 u1 = __ldcg(reinterpret_cast<const uint4*>(&g_wh[i + 1]));
    unsigned bu = __ldcg(reinterpret_cast<const unsigned*>(&g_baseh[i]));
    float2 basev = __half22float2(*reinterpret_cast<__half2*>(&bu));

    float2 acc = basev;
    // pixel 0 (x0): lf5=pa.y lf1=pc.y rt1=pd.y rt5=pf.y
    {
        float2 w01 = __half22float2(*reinterpret_cast<__half2*>(&u0.x));
        float2 w23 = __half22float2(*reinterpret_cast<__half2*>(&u0.y));
        float2 w45 = __half22float2(*reinterpret_cast<__half2*>(&u0.z));
        float2 w67 = __half22float2(*reinterpret_cast<__half2*>(&u0.w));
        acc.x = fmaf(w01.x, up5.x, acc.x);
        acc.x = fmaf(w01.y, up1.x, acc.x);
        acc.x = fmaf(w23.x, pf.y,  acc.x);
        acc.x = fmaf(w23.y, pd.y,  acc.x);
        acc.x = fmaf(w45.x, dn5.x, acc.x);
        acc.x = fmaf(w45.y, dn1.x, acc.x);
        acc.x = fmaf(w67.x, pa.y,  acc.x);
        acc.x = fmaf(w67.y, pc.y,  acc.x);
    }
    // pixel 1 (x0+1): lf5=pb.x lf1=pd.x rt1=pe.x rt5=pg.x
    {
        float2 w01 = __half22float2(*reinterpret_cast<__half2*>(&u1.x));
        float2 w23 = __half22float2(*reinterpret_cast<__half2*>(&u1.y));
        float2 w45 = __half22float2(*reinterpret_cast<__half2*>(&u1.z));
        float2 w67 = __half22float2(*reinterpret_cast<__half2*>(&u1.w));
        acc.y = fmaf(w01.x, up5.y, acc.y);
        acc.y = fmaf(w01.y, up1.y, acc.y);
        acc.y = fmaf(w23.x, pg.x,  acc.y);
        acc.y = fmaf(w23.y, pe.x,  acc.y);
        acc.y = fmaf(w45.x, dn5.y, acc.y);
        acc.y = fmaf(w45.y, dn1.y, acc.y);
        acc.y = fmaf(w67.x, pb.x,  acc.y);
        acc.y = fmaf(w67.y, pd.x,  acc.y);
    }
    return acc;
}

// Middle iterations: fp16 -> fp16 (4B store)
__global__ void __launch_bounds__(512) prop_kernel_h(const __half* __restrict__ rin,
                                                     __half* __restrict__ rout,
                                                     int b0)
{
    int x0 = (blockIdx.x * 32 + threadIdx.x) * 2;
    int y  = blockIdx.y * 16 + threadIdx.y;
    int b  = b0 + blockIdx.z;
    size_t i = (size_t)b * HWn + (size_t)y * Wn + x0;

    float2 acc = prop_body2(rin + (size_t)b * HWn, x0, y, i);
    __half2 h = __floats2half2_rn(acc.x, acc.y);
    __stcg(reinterpret_cast<__half2*>(&rout[i]), h);
}

// Final iteration: fp16 -> fp32 d_out (8B store)
__global__ void __launch_bounds__(512) prop_kernel_f(const __half* __restrict__ rin,
                                                     float* __restrict__ rout,
                                                     int b0)
{
    int x0 = (blockIdx.x * 32 + threadIdx.x) * 2;
    int y  = blockIdx.y * 16 + threadIdx.y;
    int b  = b0 + blockIdx.z;
    size_t i = (size_t)b * HWn + (size_t)y * Wn + x0;

    float2 acc = prop_body2(rin + (size_t)b * HWn, x0, y, i);
    __stcg(reinterpret_cast<float2*>(&rout[i]), acc);
}

// ---------------------------------------------------------------------------
// Launch: per 4-batch group: fused precompute+iter1, 22 h2 prop steps,
// final h2 -> fp32 step into d_out. Group set ~47MB, L2-resident.
// ---------------------------------------------------------------------------
extern "C" void kernel_launch(void* const* d_in, const int* in_sizes, int n_in,
                              void* d_out, int out_size)
{
    const float* guid   = (const float*)d_in[0];   // (B,8,H,W)
    const float* blur   = (const float*)d_in[1];   // (B,1,H,W)
    const float* sparse = (const float*)d_in[2];   // (B,1,H,W)
    float* out = (float*)d_out;                    // (B,1,H,W)

    __half *bufA, *bufB;
    cudaGetSymbolAddress((void**)&bufA, g_bufA);
    cudaGetSymbolAddress((void**)&bufB, g_bufB);

    dim3 blkF(32, 16);
    dim3 grdF(Wn / 32, Hn / 16, GROUP);    // fused kernel: 1 px/thread

    dim3 blkP(32, 16);
    dim3 grdP(Wn / 64, Hn / 16, GROUP);    // prop kernels: 2 px/thread

    for (int g = 0; g < Bn / GROUP; ++g) {
        int b0 = g * GROUP;

        fused_pre_prop1_kernel<<<grdF, blkF>>>(guid, blur, sparse, bufA, b0);
        const __half* cur = bufA;

        for (int it = 1; it < PROP_TIME - 1; ++it) {
            __half* dst = (it & 1) ? bufB : bufA;
            prop_kernel_h<<<grdP, blkP>>>(cur, dst, b0);
            cur = dst;
        }

        prop_kernel_f<<<grdP, blkP>>>(cur, out, b0);
    }
}

// round 17
// speedup vs baseline: 1.6625x; 1.0008x over previous
#include <cuda_runtime.h>
#include <cuda_fp16.h>

// Problem constants (from reference setup_inputs)
#define Bn 8
#define Hn 768
#define Wn 768
#define NPIX (Bn * Hn * Wn)          // 4,718,592
#define HWn (Hn * Wn)
#define PROP_TIME 24
#define GROUP 4                       // per-group working set ~47MB, L2-resident

// 8 fp16 weights per pixel, one 16B vector load
struct __align__(16) W8 { __half2 h[4]; };

// Scratch: __device__ globals (allocation-free per harness rules).
__device__ W8     g_wh[NPIX];         // ~75.5 MB total, 37.7 MB per group
__device__ __half g_baseh[NPIX];      // ~9.4 MB (fp16 base)
__device__ __half g_bufA[NPIX];       // ~9.4 MB (fp16 state ping)
__device__ __half g_bufB[NPIX];       // ~9.4 MB (fp16 state pong)

// 8-neighbor offsets (dy, dx), reference order
__constant__ int c_dy[8] = {-5, -1, 0, 0, 5, 1,  0,  0};
__constant__ int c_dx[8] = { 0,  0, 5, 1, 0, 0, -5, -1};

// ---------------------------------------------------------------------------
// Fused precompute + first propagation step (per group), 1 px/thread.
// fp16-rounded weights, fp16 base from ROUNDED weights, emits fp16 r1.
// ---------------------------------------------------------------------------
__global__ void __launch_bounds__(512) fused_pre_prop1_kernel(
    const float* __restrict__ guid,
    const float* __restrict__ blur,
    const float* __restrict__ sparse,
    __half* __restrict__ rout,
    int b0)
{
    int x = blockIdx.x * 32 + threadIdx.x;
    int y = blockIdx.y * 16 + threadIdx.y;
    int b = b0 + blockIdx.z;

    size_t boff = (size_t)b * HWn;
    size_t i = boff + (size_t)y * Wn + x;
    const float* gb = guid + (size_t)b * 8 * HWn;
    const float* bb = blur + boff;

    float w[8];
    float s = 0.0f;
#pragma unroll
    for (int c = 0; c < 8; ++c) {
        int yy = y + c_dy[c];
        int xx = x + c_dx[c];
        float v = 0.0f;
        if ((unsigned)yy < (unsigned)Hn && (unsigned)xx < (unsigned)Wn)
            v = __ldcs(&gb[(size_t)c * HWn + yy * Wn + xx]);
        w[c] = v;
        s += fabsf(v);
    }
    float inv = 1.0f / fmaxf(s, 1e-6f);
#pragma unroll
    for (int c = 0; c < 8; ++c) w[c] *= inv;

    float raw  = __ldcs(&blur[i]);
    bool  mask = __ldcs(&sparse[i]) > 0.0f;   // sign() of a non-negative field

    if (mask) {
#pragma unroll
        for (int c = 0; c < 8; ++c) w[c] = 0.0f;
    }

    // round weights to fp16; gate_sum from the ROUNDED weights
    W8 pack;
    float wr[8];
    float gs = 0.0f;
#pragma unroll
    for (int c = 0; c < 4; ++c) {
        __half2 h = __floats2half2_rn(w[2 * c], w[2 * c + 1]);
        pack.h[c] = h;
        float2 back = __half22float2(h);
        wr[2 * c]     = back.x;
        wr[2 * c + 1] = back.y;
        gs += back.x + back.y;
    }

    float basef_full = mask ? raw : (1.0f - gs) * raw;
    __half bh = __float2half_rn(basef_full);
    float basef = __half2float(bh);

    g_wh[i]    = pack;
    g_baseh[i] = bh;

    // r1 = base + sum_c w_c * blur_tap_c   (zero padding outside image)
    int yw = y * Wn;
    float up5 = (y >= 5)      ? __ldcs(&bb[yw - 5 * Wn + x]) : 0.0f;
    float up1 = (y >= 1)      ? __ldcs(&bb[yw - Wn + x])     : 0.0f;
    float rt5 = (x + 5 < Wn)  ? __ldcs(&bb[yw + x + 5])      : 0.0f;
    float rt1 = (x + 1 < Wn)  ? __ldcs(&bb[yw + x + 1])      : 0.0f;
    float dn5 = (y + 5 < Hn)  ? __ldcs(&bb[yw + 5 * Wn + x]) : 0.0f;
    float dn1 = (y + 1 < Hn)  ? __ldcs(&bb[yw + Wn + x])     : 0.0f;
    float lf5 = (x >= 5)      ? __ldcs(&bb[yw + x - 5])      : 0.0f;
    float lf1 = (x >= 1)      ? __ldcs(&bb[yw + x - 1])      : 0.0f;

    float acc = basef;
    acc = fmaf(wr[0], up5, acc);
    acc = fmaf(wr[1], up1, acc);
    acc = fmaf(wr[2], rt5, acc);
    acc = fmaf(wr[3], rt1, acc);
    acc = fmaf(wr[4], dn5, acc);
    acc = fmaf(wr[5], dn1, acc);
    acc = fmaf(wr[6], lf5, acc);
    acc = fmaf(wr[7], lf1, acc);

    rout[i] = __float2half_rn(acc);
}

// guarded 4B h2 load (evict-first); pair fully in- or out-of-image
__device__ __forceinline__ unsigned h2u(const __half* p, bool ok)
{
    return ok ? __ldcs(reinterpret_cast<const unsigned*>(p)) : 0u;
}
__device__ __forceinline__ float2 u2f(unsigned u)
{
    return __half22float2(*reinterpret_cast<__half2*>(&u));
}

// ---------------------------------------------------------------------------
// One propagation step, 4 x-adjacent px/thread (x0 % 4 == 0).
// Accesses per 4px: 4x LDG.128 (w) + 1x LDG.64 (base) + 4x LDG.64 (vert)
// + 8x LDG.32 (horiz h2) + 1 store  = 18  (4.5 per pixel).
// ---------------------------------------------------------------------------
__device__ __forceinline__ float4 prop_body4(const __half* __restrict__ rb,
                                             int x0, int y, size_t i)
{
    const __half* row = rb + (size_t)y * Wn;

    // vertical taps: 4 halfs per row, 8B-aligned (x0 % 4 == 0)
    uint2 vu5 = (y >= 5)     ? __ldcs(reinterpret_cast<const uint2*>(row - 5 * Wn + x0)) : make_uint2(0, 0);
    uint2 vu1 = (y >= 1)     ? __ldcs(reinterpret_cast<const uint2*>(row - Wn + x0))     : make_uint2(0, 0);
    uint2 vd5 = (y + 5 < Hn) ? __ldcs(reinterpret_cast<const uint2*>(row + 5 * Wn + x0)) : make_uint2(0, 0);
    uint2 vd1 = (y + 1 < Hn) ? __ldcs(reinterpret_cast<const uint2*>(row + Wn + x0))     : make_uint2(0, 0);

    // horizontal window x0-6 .. x0+9 as 8 h2 pairs
    unsigned p0 = h2u(row + x0 - 6, x0 >= 6);
    unsigned p1 = h2u(row + x0 - 4, x0 >= 4);
    unsigned p2 = h2u(row + x0 - 2, x0 >= 2);
    unsigned p3 = h2u(row + x0,     true);
    unsigned p4 = h2u(row + x0 + 2, true);          // x0+3 <= 767
    unsigned p5 = h2u(row + x0 + 4, x0 + 4 < Wn);
    unsigned p6 = h2u(row + x0 + 6, x0 + 6 < Wn);
    unsigned p7 = h2u(row + x0 + 8, x0 + 8 < Wn);

    // weights + base (L2-resident streams)
    uint4 u0 = __ldcg(reinterpret_cast<const uint4*>(&g_wh[i]));
    uint4 u1 = __ldcg(reinterpret_cast<const uint4*>(&g_wh[i + 1]));
    uint4 u2 = __ldcg(reinterpret_cast<const uint4*>(&g_wh[i + 2]));
    uint4 u3 = __ldcg(reinterpret_cast<const uint4*>(&g_wh[i + 3]));
    uint2 bu = __ldcg(reinterpret_cast<const uint2*>(&g_baseh[i]));

    float2 b01 = u2f(bu.x), b23 = u2f(bu.y);
    float2 u5a = u2f(vu5.x), u5b = u2f(vu5.y);
    float2 u1a = u2f(vu1.x), u1b = u2f(vu1.y);
    float2 d5a = u2f(vd5.x), d5b = u2f(vd5.y);
    float2 d1a = u2f(vd1.x), d1b = u2f(vd1.y);
    float2 f0 = u2f(p0), f1 = u2f(p1), f2 = u2f(p2), f3 = u2f(p3);
    float2 f4 = u2f(p4), f5 = u2f(p5), f6 = u2f(p6), f7 = u2f(p7);

    float4 acc;
    // pixel 0 (x0): lf5=f0.y lf1=f2.y rt1=f3.y rt5=f5.y
    {
        float2 w01 = u2f(u0.x), w23 = u2f(u0.y), w45 = u2f(u0.z), w67 = u2f(u0.w);
        float a = b01.x;
        a = fmaf(w01.x, u5a.x, a);
        a = fmaf(w01.y, u1a.x, a);
        a = fmaf(w23.x, f5.y,  a);
        a = fmaf(w23.y, f3.y,  a);
        a = fmaf(w45.x, d5a.x, a);
        a = fmaf(w45.y, d1a.x, a);
        a = fmaf(w67.x, f0.y,  a);
        a = fmaf(w67.y, f2.y,  a);
        acc.x = a;
    }
    // pixel 1 (x0+1): lf5=f1.x lf1=f3.x rt1=f4.x rt5=f6.x
    {
        float2 w01 = u2f(u1.x), w23 = u2f(u1.y), w45 = u2f(u1.z), w67 = u2f(u1.w);
        float a = b01.y;
        a = fmaf(w01.x, u5a.y, a);
        a = fmaf(w01.y, u1a.y, a);
        a = fmaf(w23.x, f6.x,  a);
        a = fmaf(w23.y, f4.x,  a);
        a = fmaf(w45.x, d5a.y, a);
        a = fmaf(w45.y, d1a.y, a);
        a = fmaf(w67.x, f1.x,  a);
        a = fmaf(w67.y, f3.x,  a);
        acc.y = a;
    }
    // pixel 2 (x0+2): lf5=f1.y lf1=f3.y rt1=f4.y rt5=f6.y
    {
        float2 w01 = u2f(u2.x), w23 = u2f(u2.y), w45 = u2f(u2.z), w67 = u2f(u2.w);
        float a = b23.x;
        a = fmaf(w01.x, u5b.x, a);
        a = fmaf(w01.y, u1b.x, a);
        a = fmaf(w23.x, f6.y,  a);
        a = fmaf(w23.y, f4.y,  a);
        a = fmaf(w45.x, d5b.x, a);
        a = fmaf(w45.y, d1b.x, a);
        a = fmaf(w67.x, f1.y,  a);
        a = fmaf(w67.y, f3.y,  a);
        acc.z = a;
    }
    // pixel 3 (x0+3): lf5=f2.x lf1=f4.x rt1=f5.x rt5=f7.x
    {
        float2 w01 = u2f(u3.x), w23 = u2f(u3.y), w45 = u2f(u3.z), w67 = u2f(u3.w);
        float a = b23.y;
        a = fmaf(w01.x, u5b.y, a);
        a = fmaf(w01.y, u1b.y, a);
        a = fmaf(w23.x, f7.x,  a);
        a = fmaf(w23.y, f5.x,  a);
        a = fmaf(w45.x, d5b.y, a);
        a = fmaf(w45.y, d1b.y, a);
        a = fmaf(w67.x, f2.x,  a);
        a = fmaf(w67.y, f4.x,  a);
        acc.w = a;
    }
    return acc;
}

// Middle iterations: fp16 -> fp16 (8B store)
__global__ void __launch_bounds__(256) prop_kernel_h(const __half* __restrict__ rin,
                                                     __half* __restrict__ rout,
                                                     int b0)
{
    int x0 = (blockIdx.x * 32 + threadIdx.x) * 4;
    int y  = blockIdx.y * 8 + threadIdx.y;
    int b  = b0 + blockIdx.z;
    size_t i = (size_t)b * HWn + (size_t)y * Wn + x0;

    float4 acc = prop_body4(rin + (size_t)b * HWn, x0, y, i);
    __half2 h01 = __floats2half2_rn(acc.x, acc.y);
    __half2 h23 = __floats2half2_rn(acc.z, acc.w);
    uint2 st = make_uint2(*reinterpret_cast<unsigned*>(&h01),
                          *reinterpret_cast<unsigned*>(&h23));
    __stcg(reinterpret_cast<uint2*>(&rout[i]), st);
}

// Final iteration: fp16 -> fp32 d_out (16B store)
__global__ void __launch_bounds__(256) prop_kernel_f(const __half* __restrict__ rin,
                                                     float* __restrict__ rout,
                                                     int b0)
{
    int x0 = (blockIdx.x * 32 + threadIdx.x) * 4;
    int y  = blockIdx.y * 8 + threadIdx.y;
    int b  = b0 + blockIdx.z;
    size_t i = (size_t)b * HWn + (size_t)y * Wn + x0;

    float4 acc = prop_body4(rin + (size_t)b * HWn, x0, y, i);
    __stcg(reinterpret_cast<float4*>(&rout[i]), acc);
}

// ---------------------------------------------------------------------------
// Launch: per 4-batch group: fused precompute+iter1, 22 h2 prop steps,
// final h2 -> fp32 step into d_out. Group set ~47MB, L2-resident.
// ---------------------------------------------------------------------------
extern "C" void kernel_launch(void* const* d_in, const int* in_sizes, int n_in,
                              void* d_out, int out_size)
{
    const float* guid   = (const float*)d_in[0];   // (B,8,H,W)
    const float* blur   = (const float*)d_in[1];   // (B,1,H,W)
    const float* sparse = (const float*)d_in[2];   // (B,1,H,W)
    float* out = (float*)d_out;                    // (B,1,H,W)

    __half *bufA, *bufB;
    cudaGetSymbolAddress((void**)&bufA, g_bufA);
    cudaGetSymbolAddress((void**)&bufB, g_bufB);

    dim3 blkF(32, 16);
    dim3 grdF(Wn / 32, Hn / 16, GROUP);    // fused kernel: 1 px/thread

    dim3 blkP(32, 8);
    dim3 grdP(Wn / 128, Hn / 8, GROUP);    // prop kernels: 4 px/thread, tile 128x8

    for (int g = 0; g < Bn / GROUP; ++g) {
        int b0 = g * GROUP;

        fused_pre_prop1_kernel<<<grdF, blkF>>>(guid, blur, sparse, bufA, b0);
        const __half* cur = bufA;

        for (int it = 1; it < PROP_TIME - 1; ++it) {
            __half* dst = (it & 1) ? bufB : bufA;
            prop_kernel_h<<<grdP, blkP>>>(cur, dst, b0);
            cur = dst;
        }

        prop_kernel_f<<<grdP, blkP>>>(cur, out, b0);
    }
}